// round 6
// baseline (speedup 1.0000x reference)
#include <cuda_runtime.h>
#include <cstdint>

#define MDIM 16384
#define NDIM 4096
#define KDIM 4096

// Module-load scratch (allowed): expanded weight + tf32-rounded x.
__device__ float g_weff[(size_t)NDIM * KDIM];   // 64 MB, [N, K] row-major
__device__ float g_x[(size_t)MDIM * KDIM];      // 256 MB, [M, K] row-major

// ---------------------------------------------------------------------------
// helpers
// ---------------------------------------------------------------------------
__device__ __forceinline__ uint32_t smem_u32(const void* p) {
    uint32_t a;
    asm("{ .reg .u64 t; cvta.to.shared.u64 t, %1; cvt.u32.u64 %0, t; }" : "=r"(a) : "l"(p));
    return a;
}
__device__ __forceinline__ float to_tf32(float x) {
    uint32_t r;
    asm("cvt.rn.tf32.f32 %0, %1;" : "=r"(r) : "f"(x));
    return __uint_as_float(r);
}
__device__ __forceinline__ void cp16(uint32_t s, const void* g) {
    asm volatile("cp.async.cg.shared.global [%0], [%1], 16;" :: "r"(s), "l"(g) : "memory");
}
#define CP_COMMIT() asm volatile("cp.async.commit_group;" ::: "memory")

__device__ __forceinline__ void ldsm4(uint32_t* r, uint32_t addr) {
    asm volatile("ldmatrix.sync.aligned.m8n8.x4.shared.b16 {%0,%1,%2,%3}, [%4];"
        : "=r"(r[0]), "=r"(r[1]), "=r"(r[2]), "=r"(r[3]) : "r"(addr));
}
__device__ __forceinline__ void mma_tf32(float* d, const uint32_t* a, const uint32_t* b) {
    asm volatile(
        "mma.sync.aligned.m16n8k8.row.col.f32.tf32.tf32.f32 "
        "{%0,%1,%2,%3}, {%4,%5,%6,%7}, {%8,%9}, {%0,%1,%2,%3};"
        : "+f"(d[0]), "+f"(d[1]), "+f"(d[2]), "+f"(d[3])
        : "r"(a[0]), "r"(a[1]), "r"(a[2]), "r"(a[3]), "r"(b[0]), "r"(b[1]));
}

// ---------------------------------------------------------------------------
// Kernel 0: round x to nearest tf32 into g_x.
// ---------------------------------------------------------------------------
__global__ void round_x_kernel(const float* __restrict__ x) {
    size_t i = (size_t)blockIdx.x * blockDim.x + threadIdx.x;
    float4 v = reinterpret_cast<const float4*>(x)[i];
    v.x = to_tf32(v.x); v.y = to_tf32(v.y); v.z = to_tf32(v.z); v.w = to_tf32(v.w);
    reinterpret_cast<float4*>(g_x)[i] = v;
}

// ---------------------------------------------------------------------------
// Kernel 1: expand octonion weight [512,512,8] -> w_eff [4096,4096], tf32-rounded.
// ---------------------------------------------------------------------------
__global__ void build_weff_kernel(const float* __restrict__ w) {
    const signed char KTAB[64] = {
        0,1,2,3,4,5,6,7, 1,0,3,2,5,4,7,6, 2,3,0,1,6,7,4,5, 3,2,1,0,7,6,5,4,
        4,5,6,7,0,1,2,3, 5,4,7,6,1,0,3,2, 6,7,4,5,2,3,0,1, 7,6,5,4,3,2,1,0 };
    const signed char STAB[64] = {
        +1,+1,+1,+1,+1,+1,+1,+1, +1,-1,+1,-1,+1,-1,-1,+1, +1,-1,-1,+1,+1,+1,-1,-1,
        +1,+1,-1,-1,+1,-1,+1,-1, +1,-1,-1,-1,-1,+1,+1,+1, +1,+1,-1,+1,-1,-1,-1,+1,
        +1,+1,+1,-1,-1,+1,-1,-1, +1,-1,+1,+1,-1,-1,+1,-1 };

    int t = blockIdx.x * blockDim.x + threadIdx.x;
    if (t >= 512 * 512) return;
    int o = t >> 9, i = t & 511;

    const float4* wp = reinterpret_cast<const float4*>(w + (size_t)t * 8);
    float4 wlo = wp[0], whi = wp[1];
    float wv[8] = {wlo.x, wlo.y, wlo.z, wlo.w, whi.x, whi.y, whi.z, whi.w};

    #pragma unroll
    for (int k = 0; k < 8; ++k) {
        float out[8];
        #pragma unroll
        for (int b = 0; b < 8; ++b) {
            int a = KTAB[k * 8 + b];
            out[b] = to_tf32((float)STAB[a * 8 + b] * wv[a]);
        }
        float4* dst = reinterpret_cast<float4*>(g_weff + (size_t)(o * 8 + k) * KDIM + i * 8);
        dst[0] = make_float4(out[0], out[1], out[2], out[3]);
        dst[1] = make_float4(out[4], out[5], out[6], out[7]);
    }
}

// ---------------------------------------------------------------------------
// Kernel 2: tf32 mma.sync GEMM. C[M,N] = g_x[M,K] @ g_weff[N,K]^T + bias.
// CTA 128(M) x 256(N), BK=32. 8 warps = 2(M) x 4(N); warp tile 64x64
// = 4x8 m16n8k8 atoms. 4-stage cp.async pipeline, XOR-swizzled smem.
// ---------------------------------------------------------------------------
#define BK 32
#define STAGES 4
#define A_BYTES (128 * BK * 4)              // 16384
#define B_BYTES (256 * BK * 4)              // 32768
#define STAGE_BYTES (A_BYTES + B_BYTES)     // 49152
#define GEMM_SMEM (STAGES * STAGE_BYTES)    // 196608
#define NTILES (KDIM / BK)                  // 128

__global__ __launch_bounds__(256, 1) void gemm_mma_kernel(
    const float* __restrict__ bias, float* __restrict__ C)
{
    extern __shared__ char smem[];
    const uint32_t sb = smem_u32(smem);
    const int tid  = threadIdx.x;
    const int lane = tid & 31;
    const int wid  = tid >> 5;
    const int rowBase = blockIdx.y * 128;    // M
    const int colBase = blockIdx.x * 256;    // N
    const int warpM = (wid >> 2) * 64;
    const int warpN = (wid & 3) * 64;

    // ---- global->shared mapping ----
    // A: thread covers row (tid>>1), 4 chunks starting at (tid&1)*4.
    const int lrA  = tid >> 1;
    const int lcpA = (tid & 1) * 4;
    const float* gA = g_x + (size_t)(rowBase + lrA) * KDIM + lcpA * 4;
    // B: thread covers row tid, all 8 chunks.
    const float* gB = g_weff + (size_t)(colBase + tid) * KDIM;
    uint32_t sAo[4], sBo[8];
    #pragma unroll
    for (int j = 0; j < 4; ++j)
        sAo[j] = sb + lrA * 128 + (uint32_t)(((lcpA + j) ^ (lrA & 7)) << 4);
    #pragma unroll
    for (int j = 0; j < 8; ++j)
        sBo[j] = sb + A_BYTES + tid * 128 + (uint32_t)((j ^ (tid & 7)) << 4);

    // ---- ldmatrix address bases ----
    const int swz = lane & 7;
    uint32_t aBase[4], bBase[4];
    {
        int rA = warpM + (lane & 15);                       // lanes 16-31: chunk-hi
        #pragma unroll
        for (int am = 0; am < 4; ++am)
            aBase[am] = sb + (uint32_t)((rA + am * 16) * 128);
        // B pair p covers n-atoms 2p,2p+1: rows warpN + p*16 + (lane&7) + ((lane>>4)&1)*8
        int rB = warpN + (lane & 7) + ((lane >> 4) & 1) * 8;
        #pragma unroll
        for (int p = 0; p < 4; ++p)
            bBase[p] = sb + A_BYTES + (uint32_t)((rB + p * 16) * 128);
    }
    const int laneAhi = lane >> 4;           // A: chunk +0/+1 select
    const int laneBhi = (lane >> 3) & 1;     // B: chunk +0/+1 select

    float acc[4][8][4];
    #pragma unroll
    for (int am = 0; am < 4; ++am)
        #pragma unroll
        for (int an = 0; an < 8; ++an)
            #pragma unroll
            for (int e = 0; e < 4; ++e) acc[am][an][e] = 0.0f;

    // ---- prologue: prefetch STAGES-1 tiles ----
    #pragma unroll
    for (int t = 0; t < STAGES - 1; ++t) {
        uint32_t so = (uint32_t)(t * STAGE_BYTES);
        const float* a = gA + t * BK;
        const float* b = gB + t * BK;
        #pragma unroll
        for (int j = 0; j < 4; ++j) cp16(sAo[j] + so, a + j * 4);
        #pragma unroll
        for (int j = 0; j < 8; ++j) cp16(sBo[j] + so, b + j * 4);
        CP_COMMIT();
    }

    // ---- mainloop ----
    #pragma unroll 1
    for (int t = 0; t < NTILES; ++t) {
        asm volatile("cp.async.wait_group 2;" ::: "memory");
        __syncthreads();

        if (t + STAGES - 1 < NTILES) {
            int tn = t + STAGES - 1;
            uint32_t so = (uint32_t)((tn & (STAGES - 1)) * STAGE_BYTES);
            const float* a = gA + tn * BK;
            const float* b = gB + tn * BK;
            #pragma unroll
            for (int j = 0; j < 4; ++j) cp16(sAo[j] + so, a + j * 4);
            #pragma unroll
            for (int j = 0; j < 8; ++j) cp16(sBo[j] + so, b + j * 4);
        }
        CP_COMMIT();

        const uint32_t so = (uint32_t)((t & (STAGES - 1)) * STAGE_BYTES);
        #pragma unroll
        for (int ks = 0; ks < 4; ++ks) {
            uint32_t a_frag[4][4], b_frag[4][4];
            const uint32_t qa = (uint32_t)(((2 * ks + laneAhi) ^ swz) << 4);
            const uint32_t qb = (uint32_t)(((2 * ks + laneBhi) ^ swz) << 4);
            #pragma unroll
            for (int am = 0; am < 4; ++am) ldsm4(a_frag[am], aBase[am] + so + qa);
            #pragma unroll
            for (int p = 0; p < 4; ++p)   ldsm4(b_frag[p],  bBase[p]  + so + qb);
            #pragma unroll
            for (int am = 0; am < 4; ++am)
                #pragma unroll
                for (int an = 0; an < 8; ++an)
                    mma_tf32(acc[am][an], a_frag[am], &b_frag[an >> 1][(an & 1) * 2]);
        }
    }

    // ---- epilogue: bias + store ----
    float2 bv[8];
    #pragma unroll
    for (int an = 0; an < 8; ++an)
        bv[an] = *reinterpret_cast<const float2*>(
            bias + colBase + warpN + an * 8 + (lane & 3) * 2);

    #pragma unroll
    for (int am = 0; am < 4; ++am) {
        const int r0 = rowBase + warpM + am * 16 + (lane >> 2);
        #pragma unroll
        for (int an = 0; an < 8; ++an) {
            const int col = colBase + warpN + an * 8 + (lane & 3) * 2;
            float2 lo = make_float2(acc[am][an][0] + bv[an].x, acc[am][an][1] + bv[an].y);
            float2 hi = make_float2(acc[am][an][2] + bv[an].x, acc[am][an][3] + bv[an].y);
            *reinterpret_cast<float2*>(C + (size_t)r0 * NDIM + col) = lo;
            *reinterpret_cast<float2*>(C + (size_t)(r0 + 8) * NDIM + col) = hi;
        }
    }
}

extern "C" void kernel_launch(void* const* d_in, const int* in_sizes, int n_in,
                              void* d_out, int out_size) {
    const float* x    = (const float*)d_in[0];   // [8,2048,4096]
    const float* w    = (const float*)d_in[1];   // [512,512,8]
    const float* bias = (const float*)d_in[2];   // [4096]
    float* out = (float*)d_out;                  // [16384,4096] fp32

    cudaFuncSetAttribute(gemm_mma_kernel,
                         cudaFuncAttributeMaxDynamicSharedMemorySize, GEMM_SMEM);

    round_x_kernel<<<(int)(((size_t)MDIM * KDIM / 4) / 256), 256>>>(x);
    build_weff_kernel<<<(512 * 512 + 255) / 256, 256>>>(w);

    dim3 grid(NDIM / 256, MDIM / 128);           // (16, 128)
    gemm_mma_kernel<<<grid, 256, GEMM_SMEM>>>(bias, out);
}

// round 7
// speedup vs baseline: 2.1119x; 2.1119x over previous
#include <cuda_runtime.h>
#include <cuda_fp16.h>
#include <cstdint>

#define MDIM 16384
#define NDIM 4096
#define KDIM 4096

// Module-load scratch (allowed): fp16 copies of x and expanded weight.
__device__ __half g_xh[(size_t)MDIM * KDIM];    // 128 MB, [M, K] row-major
__device__ __half g_wh[(size_t)NDIM * KDIM];    // 32 MB,  [N, K] row-major

// ---------------------------------------------------------------------------
// helpers
// ---------------------------------------------------------------------------
__device__ __forceinline__ uint32_t smem_u32(const void* p) {
    uint32_t a;
    asm("{ .reg .u64 t; cvta.to.shared.u64 t, %1; cvt.u32.u64 %0, t; }" : "=r"(a) : "l"(p));
    return a;
}
__device__ __forceinline__ void cp16(uint32_t s, const void* g) {
    asm volatile("cp.async.cg.shared.global [%0], [%1], 16;" :: "r"(s), "l"(g) : "memory");
}
#define CP_COMMIT() asm volatile("cp.async.commit_group;" ::: "memory")

__device__ __forceinline__ void ldsm4(uint32_t* r, uint32_t addr) {
    asm volatile("ldmatrix.sync.aligned.m8n8.x4.shared.b16 {%0,%1,%2,%3}, [%4];"
        : "=r"(r[0]), "=r"(r[1]), "=r"(r[2]), "=r"(r[3]) : "r"(addr));
}
__device__ __forceinline__ void ldsm2(uint32_t* r, uint32_t addr) {
    asm volatile("ldmatrix.sync.aligned.m8n8.x2.shared.b16 {%0,%1}, [%2];"
        : "=r"(r[0]), "=r"(r[1]) : "r"(addr));
}
__device__ __forceinline__ void mma_f16(float* d, const uint32_t* a, const uint32_t* b) {
    asm volatile(
        "mma.sync.aligned.m16n8k16.row.col.f32.f16.f16.f32 "
        "{%0,%1,%2,%3}, {%4,%5,%6,%7}, {%8,%9}, {%0,%1,%2,%3};"
        : "+f"(d[0]), "+f"(d[1]), "+f"(d[2]), "+f"(d[3])
        : "r"(a[0]), "r"(a[1]), "r"(a[2]), "r"(a[3]), "r"(b[0]), "r"(b[1]));
}

// ---------------------------------------------------------------------------
// Kernel 0: convert x fp32 -> fp16 (RN). 8 elements per thread.
// ---------------------------------------------------------------------------
__global__ void conv_x_kernel(const float* __restrict__ x) {
    size_t i = (size_t)blockIdx.x * blockDim.x + threadIdx.x;   // 8-elem index
    float4 a = reinterpret_cast<const float4*>(x)[2 * i];
    float4 b = reinterpret_cast<const float4*>(x)[2 * i + 1];
    __half2 h0 = __floats2half2_rn(a.x, a.y);
    __half2 h1 = __floats2half2_rn(a.z, a.w);
    __half2 h2 = __floats2half2_rn(b.x, b.y);
    __half2 h3 = __floats2half2_rn(b.z, b.w);
    uint4 o;
    o.x = *reinterpret_cast<uint32_t*>(&h0);
    o.y = *reinterpret_cast<uint32_t*>(&h1);
    o.z = *reinterpret_cast<uint32_t*>(&h2);
    o.w = *reinterpret_cast<uint32_t*>(&h3);
    reinterpret_cast<uint4*>(g_xh)[i] = o;
}

// ---------------------------------------------------------------------------
// Kernel 1: expand octonion weight [512,512,8] -> w_eff [4096,4096] in fp16.
// ---------------------------------------------------------------------------
__global__ void build_weff_kernel(const float* __restrict__ w) {
    const signed char KTAB[64] = {
        0,1,2,3,4,5,6,7, 1,0,3,2,5,4,7,6, 2,3,0,1,6,7,4,5, 3,2,1,0,7,6,5,4,
        4,5,6,7,0,1,2,3, 5,4,7,6,1,0,3,2, 6,7,4,5,2,3,0,1, 7,6,5,4,3,2,1,0 };
    const signed char STAB[64] = {
        +1,+1,+1,+1,+1,+1,+1,+1, +1,-1,+1,-1,+1,-1,-1,+1, +1,-1,-1,+1,+1,+1,-1,-1,
        +1,+1,-1,-1,+1,-1,+1,-1, +1,-1,-1,-1,-1,+1,+1,+1, +1,+1,-1,+1,-1,-1,-1,+1,
        +1,+1,+1,-1,-1,+1,-1,-1, +1,-1,+1,+1,-1,-1,+1,-1 };

    int t = blockIdx.x * blockDim.x + threadIdx.x;
    if (t >= 512 * 512) return;
    int o = t >> 9, i = t & 511;

    const float4* wp = reinterpret_cast<const float4*>(w + (size_t)t * 8);
    float4 wlo = wp[0], whi = wp[1];
    float wv[8] = {wlo.x, wlo.y, wlo.z, wlo.w, whi.x, whi.y, whi.z, whi.w};

    #pragma unroll
    for (int k = 0; k < 8; ++k) {
        __half2 h[4];
        #pragma unroll
        for (int bp = 0; bp < 4; ++bp) {
            int b0 = 2 * bp, b1 = 2 * bp + 1;
            int a0 = KTAB[k * 8 + b0], a1 = KTAB[k * 8 + b1];
            float v0 = (float)STAB[a0 * 8 + b0] * wv[a0];
            float v1 = (float)STAB[a1 * 8 + b1] * wv[a1];
            h[bp] = __floats2half2_rn(v0, v1);
        }
        uint4 pk;
        pk.x = *reinterpret_cast<uint32_t*>(&h[0]);
        pk.y = *reinterpret_cast<uint32_t*>(&h[1]);
        pk.z = *reinterpret_cast<uint32_t*>(&h[2]);
        pk.w = *reinterpret_cast<uint32_t*>(&h[3]);
        *reinterpret_cast<uint4*>(g_wh + (size_t)(o * 8 + k) * KDIM + i * 8) = pk;
    }
}

// ---------------------------------------------------------------------------
// Kernel 2: fp16 mma.sync GEMM. C[M,N] = g_xh[M,K] @ g_wh[N,K]^T + bias.
// CTA 128x128, BK=64 halves (128 B per smem row, XOR-swizzled).
// 8 warps = 2(M) x 4(N); warp tile 64x32 = 4x4 m16n8k16 atoms.
// 4-stage cp.async pipeline. Byte-level layout identical to the proven
// R5 tf32 kernel; only the element width and mma opcode change.
// ---------------------------------------------------------------------------
#define BK 64
#define STAGES 4
#define A_BYTES (128 * 128)                 // 16384: 128 rows x 128 B
#define STAGE_BYTES (2 * A_BYTES)           // 32768: [A | B]
#define GEMM_SMEM (STAGES * STAGE_BYTES)    // 131072
#define NTILES (KDIM / BK)                  // 64

__global__ __launch_bounds__(256, 1) void gemm_mma_kernel(
    const float* __restrict__ bias, float* __restrict__ C)
{
    extern __shared__ char smem[];
    const uint32_t sb = smem_u32(smem);
    const int tid  = threadIdx.x;
    const int lane = tid & 31;
    const int wid  = tid >> 5;
    const int rowBase = blockIdx.y * 128;    // M
    const int colBase = blockIdx.x * 128;    // N
    const int warpM = (wid >> 2) * 64;
    const int warpN = (wid & 3) * 32;

    // ---- global->shared load mapping: thread covers 4 A-chunks + 4 B-chunks ----
    const int lr  = tid >> 1;                // row 0..127
    const int lcp = (tid & 1) * 4;           // chunk base: 0 or 4 (chunk = 16 B = 8 halves)
    const __half* gA = g_xh + (size_t)(rowBase + lr) * KDIM + lcp * 8;
    const __half* gB = g_wh + (size_t)(colBase + lr) * KDIM + lcp * 8;
    uint32_t sAo[4], sBo[4];
    #pragma unroll
    for (int j = 0; j < 4; ++j) {
        uint32_t sw = (uint32_t)(((lcp + j) ^ (lr & 7)) << 4);
        sAo[j] = sb + lr * 128 + sw;
        sBo[j] = sb + A_BYTES + lr * 128 + sw;
    }

    // ---- ldmatrix address bases ----
    const int swz = lane & 7;
    uint32_t aBase[4], bBase[4];
    {
        int rA = warpM + (lane & 15);
        #pragma unroll
        for (int am = 0; am < 4; ++am) aBase[am] = sb + (uint32_t)((rA + am * 16) * 128);
        int rB = warpN + (lane & 7);
        #pragma unroll
        for (int an = 0; an < 4; ++an) bBase[an] = sb + A_BYTES + (uint32_t)((rB + an * 8) * 128);
    }
    const int laneAhi = lane >> 4;           // A: k-chunk +0/+1 select
    const int laneBhi = (lane >> 3) & 1;     // B: k-chunk +0/+1 select

    float acc[4][4][4];
    #pragma unroll
    for (int am = 0; am < 4; ++am)
        #pragma unroll
        for (int an = 0; an < 4; ++an)
            #pragma unroll
            for (int e = 0; e < 4; ++e) acc[am][an][e] = 0.0f;

    // ---- prologue ----
    #pragma unroll
    for (int t = 0; t < STAGES - 1; ++t) {
        uint32_t so = (uint32_t)(t * STAGE_BYTES);
        const __half* a = gA + t * BK;
        const __half* b = gB + t * BK;
        #pragma unroll
        for (int j = 0; j < 4; ++j) cp16(sAo[j] + so, a + j * 8);
        #pragma unroll
        for (int j = 0; j < 4; ++j) cp16(sBo[j] + so, b + j * 8);
        CP_COMMIT();
    }

    // ---- mainloop ----
    #pragma unroll 1
    for (int t = 0; t < NTILES; ++t) {
        asm volatile("cp.async.wait_group 2;" ::: "memory");
        __syncthreads();

        if (t + STAGES - 1 < NTILES) {
            int tn = t + STAGES - 1;
            uint32_t so = (uint32_t)((tn & (STAGES - 1)) * STAGE_BYTES);
            const __half* a = gA + tn * BK;
            const __half* b = gB + tn * BK;
            #pragma unroll
            for (int j = 0; j < 4; ++j) cp16(sAo[j] + so, a + j * 8);
            #pragma unroll
            for (int j = 0; j < 4; ++j) cp16(sBo[j] + so, b + j * 8);
        }
        CP_COMMIT();

        // 4 k16 steps per tile; k16 = 32 B = 2 chunks
        const uint32_t so = (uint32_t)((t & (STAGES - 1)) * STAGE_BYTES);
        #pragma unroll
        for (int ks = 0; ks < 4; ++ks) {
            uint32_t a_frag[4][4], b_frag[4][2];
            const uint32_t qa = (uint32_t)(((2 * ks + laneAhi) ^ swz) << 4);
            const uint32_t qb = (uint32_t)(((2 * ks + laneBhi) ^ swz) << 4);
            #pragma unroll
            for (int am = 0; am < 4; ++am) ldsm4(a_frag[am], aBase[am] + so + qa);
            #pragma unroll
            for (int an = 0; an < 4; ++an) ldsm2(b_frag[an], bBase[an] + so + qb);
            #pragma unroll
            for (int am = 0; am < 4; ++am)
                #pragma unroll
                for (int an = 0; an < 4; ++an)
                    mma_f16(acc[am][an], a_frag[am], b_frag[an]);
        }
    }

    // ---- epilogue: bias + store ----
    float2 bv[4];
    #pragma unroll
    for (int an = 0; an < 4; ++an)
        bv[an] = *reinterpret_cast<const float2*>(
            bias + colBase + warpN + an * 8 + (lane & 3) * 2);

    #pragma unroll
    for (int am = 0; am < 4; ++am) {
        const int r0 = rowBase + warpM + am * 16 + (lane >> 2);
        #pragma unroll
        for (int an = 0; an < 4; ++an) {
            const int col = colBase + warpN + an * 8 + (lane & 3) * 2;
            float2 lo = make_float2(acc[am][an][0] + bv[an].x, acc[am][an][1] + bv[an].y);
            float2 hi = make_float2(acc[am][an][2] + bv[an].x, acc[am][an][3] + bv[an].y);
            *reinterpret_cast<float2*>(C + (size_t)r0 * NDIM + col) = lo;
            *reinterpret_cast<float2*>(C + (size_t)(r0 + 8) * NDIM + col) = hi;
        }
    }
}

extern "C" void kernel_launch(void* const* d_in, const int* in_sizes, int n_in,
                              void* d_out, int out_size) {
    const float* x    = (const float*)d_in[0];   // [8,2048,4096]
    const float* w    = (const float*)d_in[1];   // [512,512,8]
    const float* bias = (const float*)d_in[2];   // [4096]
    float* out = (float*)d_out;                  // [16384,4096] fp32

    cudaFuncSetAttribute(gemm_mma_kernel,
                         cudaFuncAttributeMaxDynamicSharedMemorySize, GEMM_SMEM);

    conv_x_kernel<<<(int)(((size_t)MDIM * KDIM / 8) / 256), 256>>>(x);
    build_weff_kernel<<<(512 * 512 + 255) / 256, 256>>>(w);

    dim3 grid(NDIM / 128, MDIM / 128);           // (32, 128)
    gemm_mma_kernel<<<grid, 256, GEMM_SMEM>>>(bias, out);
}

// round 10
// speedup vs baseline: 2.5575x; 1.2110x over previous
#include <cuda_runtime.h>
#include <cuda_fp16.h>
#include <cstdint>

#define MDIM 16384
#define NDIM 4096
#define KDIM 4096

// Module-load scratch (allowed): fp16 copies of x and expanded weight.
__device__ __half g_xh[(size_t)MDIM * KDIM];    // 128 MB, [M, K] row-major
__device__ __half g_wh[(size_t)NDIM * KDIM];    // 32 MB,  [N, K] row-major

// ---------------------------------------------------------------------------
// helpers
// ---------------------------------------------------------------------------
__device__ __forceinline__ uint32_t smem_u32(const void* p) {
    uint32_t a;
    asm("{ .reg .u64 t; cvta.to.shared.u64 t, %1; cvt.u32.u64 %0, t; }" : "=r"(a) : "l"(p));
    return a;
}
__device__ __forceinline__ void cp16(uint32_t s, const void* g) {
    asm volatile("cp.async.cg.shared.global [%0], [%1], 16;" :: "r"(s), "l"(g) : "memory");
}
#define CP_COMMIT() asm volatile("cp.async.commit_group;" ::: "memory")

__device__ __forceinline__ void ldsm4(uint32_t* r, uint32_t addr) {
    asm volatile("ldmatrix.sync.aligned.m8n8.x4.shared.b16 {%0,%1,%2,%3}, [%4];"
        : "=r"(r[0]), "=r"(r[1]), "=r"(r[2]), "=r"(r[3]) : "r"(addr));
}
__device__ __forceinline__ void ldsm2(uint32_t* r, uint32_t addr) {
    asm volatile("ldmatrix.sync.aligned.m8n8.x2.shared.b16 {%0,%1}, [%2];"
        : "=r"(r[0]), "=r"(r[1]) : "r"(addr));
}
__device__ __forceinline__ void mma_f16(float* d, const uint32_t* a, const uint32_t* b) {
    asm volatile(
        "mma.sync.aligned.m16n8k16.row.col.f32.f16.f16.f32 "
        "{%0,%1,%2,%3}, {%4,%5,%6,%7}, {%8,%9}, {%0,%1,%2,%3};"
        : "+f"(d[0]), "+f"(d[1]), "+f"(d[2]), "+f"(d[3])
        : "r"(a[0]), "r"(a[1]), "r"(a[2]), "r"(a[3]), "r"(b[0]), "r"(b[1]));
}

// ---------------------------------------------------------------------------
// Kernel 0: convert x fp32 -> fp16 (RN). 8 elements per thread.
// ---------------------------------------------------------------------------
__global__ void conv_x_kernel(const float* __restrict__ x) {
    size_t i = (size_t)blockIdx.x * blockDim.x + threadIdx.x;
    float4 a = reinterpret_cast<const float4*>(x)[2 * i];
    float4 b = reinterpret_cast<const float4*>(x)[2 * i + 1];
    __half2 h0 = __floats2half2_rn(a.x, a.y);
    __half2 h1 = __floats2half2_rn(a.z, a.w);
    __half2 h2 = __floats2half2_rn(b.x, b.y);
    __half2 h3 = __floats2half2_rn(b.z, b.w);
    uint4 o;
    o.x = *reinterpret_cast<uint32_t*>(&h0);
    o.y = *reinterpret_cast<uint32_t*>(&h1);
    o.z = *reinterpret_cast<uint32_t*>(&h2);
    o.w = *reinterpret_cast<uint32_t*>(&h3);
    reinterpret_cast<uint4*>(g_xh)[i] = o;
}

// ---------------------------------------------------------------------------
// Kernel 1: expand octonion weight [512,512,8] -> w_eff [4096,4096] in fp16.
// ---------------------------------------------------------------------------
__global__ void build_weff_kernel(const float* __restrict__ w) {
    const signed char KTAB[64] = {
        0,1,2,3,4,5,6,7, 1,0,3,2,5,4,7,6, 2,3,0,1,6,7,4,5, 3,2,1,0,7,6,5,4,
        4,5,6,7,0,1,2,3, 5,4,7,6,1,0,3,2, 6,7,4,5,2,3,0,1, 7,6,5,4,3,2,1,0 };
    const signed char STAB[64] = {
        +1,+1,+1,+1,+1,+1,+1,+1, +1,-1,+1,-1,+1,-1,-1,+1, +1,-1,-1,+1,+1,+1,-1,-1,
        +1,+1,-1,-1,+1,-1,+1,-1, +1,-1,-1,-1,-1,+1,+1,+1, +1,+1,-1,+1,-1,-1,-1,+1,
        +1,+1,+1,-1,-1,+1,-1,-1, +1,-1,+1,+1,-1,-1,+1,-1 };

    int t = blockIdx.x * blockDim.x + threadIdx.x;
    if (t >= 512 * 512) return;
    int o = t >> 9, i = t & 511;

    const float4* wp = reinterpret_cast<const float4*>(w + (size_t)t * 8);
    float4 wlo = wp[0], whi = wp[1];
    float wv[8] = {wlo.x, wlo.y, wlo.z, wlo.w, whi.x, whi.y, whi.z, whi.w};

    #pragma unroll
    for (int k = 0; k < 8; ++k) {
        __half2 h[4];
        #pragma unroll
        for (int bp = 0; bp < 4; ++bp) {
            int b0 = 2 * bp, b1 = 2 * bp + 1;
            int a0 = KTAB[k * 8 + b0], a1 = KTAB[k * 8 + b1];
            float v0 = (float)STAB[a0 * 8 + b0] * wv[a0];
            float v1 = (float)STAB[a1 * 8 + b1] * wv[a1];
            h[bp] = __floats2half2_rn(v0, v1);
        }
        uint4 pk;
        pk.x = *reinterpret_cast<uint32_t*>(&h[0]);
        pk.y = *reinterpret_cast<uint32_t*>(&h[1]);
        pk.z = *reinterpret_cast<uint32_t*>(&h[2]);
        pk.w = *reinterpret_cast<uint32_t*>(&h[3]);
        *reinterpret_cast<uint4*>(g_wh + (size_t)(o * 8 + k) * KDIM + i * 8) = pk;
    }
}

// ---------------------------------------------------------------------------
// Kernel 2: fp16 mma.sync GEMM. C[M,N] = g_xh[M,K] @ g_wh[N,K]^T + bias.
// CTA 128x128, BK=64 halves (128 B smem rows, XOR-swizzled).
// 8 warps = 2(M) x 4(N); warp tile 64x32 = 4x4 m16n8k16 atoms.
// 3-stage cp.async pipeline, 2 CTAs/SM.
// ---------------------------------------------------------------------------
#define BK 64
#define STAGES 3
#define A_BYTES (128 * 128)                 // 16384
#define STAGE_BYTES (2 * A_BYTES)           // 32768: [A | B]
#define GEMM_SMEM (STAGES * STAGE_BYTES)    // 98304
#define NTILES (KDIM / BK)                  // 64

__global__ __launch_bounds__(256, 2) void gemm_mma_kernel(
    const float* __restrict__ bias, float* __restrict__ C)
{
    extern __shared__ char smem[];
    const uint32_t sb = smem_u32(smem);
    const int tid  = threadIdx.x;
    const int lane = tid & 31;
    const int wid  = tid >> 5;
    const int rowBase = blockIdx.y * 128;    // M
    const int colBase = blockIdx.x * 128;    // N
    const int warpM = (wid >> 2) * 64;
    const int warpN = (wid & 3) * 32;

    // ---- global->shared load mapping: thread covers 4 A-chunks + 4 B-chunks ----
    const int lr  = tid >> 1;                // row 0..127
    const int lcp = (tid & 1) * 4;           // chunk base: 0 or 4 (chunk = 16 B)
    const __half* gA = g_xh + (size_t)(rowBase + lr) * KDIM + lcp * 8;
    const __half* gB = g_wh + (size_t)(colBase + lr) * KDIM + lcp * 8;
    uint32_t sAo[4], sBo[4];
    #pragma unroll
    for (int j = 0; j < 4; ++j) {
        uint32_t sw = (uint32_t)(((lcp + j) ^ (lr & 7)) << 4);
        sAo[j] = sb + lr * 128 + sw;
        sBo[j] = sb + A_BYTES + lr * 128 + sw;
    }

    // ---- ldmatrix address bases ----
    const int swz = lane & 7;
    uint32_t aBase[4], bBase[4];
    {
        int rA = warpM + (lane & 15);
        #pragma unroll
        for (int am = 0; am < 4; ++am) aBase[am] = sb + (uint32_t)((rA + am * 16) * 128);
        int rB = warpN + (lane & 7);
        #pragma unroll
        for (int an = 0; an < 4; ++an) bBase[an] = sb + A_BYTES + (uint32_t)((rB + an * 8) * 128);
    }
    const int laneAhi = lane >> 4;
    const int laneBhi = (lane >> 3) & 1;

    float acc[4][4][4];
    #pragma unroll
    for (int am = 0; am < 4; ++am)
        #pragma unroll
        for (int an = 0; an < 4; ++an)
            #pragma unroll
            for (int e = 0; e < 4; ++e) acc[am][an][e] = 0.0f;

    // ---- prologue: prefetch tiles 0,1 into stages 0,1 ----
    #pragma unroll
    for (int t = 0; t < STAGES - 1; ++t) {
        uint32_t so = (uint32_t)(t * STAGE_BYTES);
        const __half* a = gA + t * BK;
        const __half* b = gB + t * BK;
        #pragma unroll
        for (int j = 0; j < 4; ++j) cp16(sAo[j] + so, a + j * 8);
        #pragma unroll
        for (int j = 0; j < 4; ++j) cp16(sBo[j] + so, b + j * 8);
        CP_COMMIT();
    }

    // ---- mainloop (stage offsets cycle 0,S,2S without division) ----
    uint32_t soC = 0;                               // compute stage offset
    uint32_t soP = (STAGES - 1) * STAGE_BYTES;      // produce stage offset
    #pragma unroll 1
    for (int t = 0; t < NTILES; ++t) {
        asm volatile("cp.async.wait_group 1;" ::: "memory");
        __syncthreads();

        if (t + STAGES - 1 < NTILES) {
            int tn = t + STAGES - 1;
            const __half* a = gA + tn * BK;
            const __half* b = gB + tn * BK;
            #pragma unroll
            for (int j = 0; j < 4; ++j) cp16(sAo[j] + soP, a + j * 8);
            #pragma unroll
            for (int j = 0; j < 4; ++j) cp16(sBo[j] + soP, b + j * 8);
        }
        CP_COMMIT();

        // 4 k16 steps per tile
        #pragma unroll
        for (int ks = 0; ks < 4; ++ks) {
            uint32_t a_frag[4][4], b_frag[4][2];
            const uint32_t qa = (uint32_t)(((2 * ks + laneAhi) ^ swz) << 4);
            const uint32_t qb = (uint32_t)(((2 * ks + laneBhi) ^ swz) << 4);
            #pragma unroll
            for (int am = 0; am < 4; ++am) ldsm4(a_frag[am], aBase[am] + soC + qa);
            #pragma unroll
            for (int an = 0; an < 4; ++an) ldsm2(b_frag[an], bBase[an] + soC + qb);
            #pragma unroll
            for (int am = 0; am < 4; ++am)
                #pragma unroll
                for (int an = 0; an < 4; ++an)
                    mma_f16(acc[am][an], a_frag[am], b_frag[an]);
        }

        soC += STAGE_BYTES; if (soC == STAGES * STAGE_BYTES) soC = 0;
        soP += STAGE_BYTES; if (soP == STAGES * STAGE_BYTES) soP = 0;
    }

    // ---- epilogue: bias + store ----
    float2 bv[4];
    #pragma unroll
    for (int an = 0; an < 4; ++an)
        bv[an] = *reinterpret_cast<const float2*>(
            bias + colBase + warpN + an * 8 + (lane & 3) * 2);

    #pragma unroll
    for (int am = 0; am < 4; ++am) {
        const int r0 = rowBase + warpM + am * 16 + (lane >> 2);
        #pragma unroll
        for (int an = 0; an < 4; ++an) {
            const int col = colBase + warpN + an * 8 + (lane & 3) * 2;
            float2 lo = make_float2(acc[am][an][0] + bv[an].x, acc[am][an][1] + bv[an].y);
            float2 hi = make_float2(acc[am][an][2] + bv[an].x, acc[am][an][3] + bv[an].y);
            *reinterpret_cast<float2*>(C + (size_t)r0 * NDIM + col) = lo;
            *reinterpret_cast<float2*>(C + (size_t)(r0 + 8) * NDIM + col) = hi;
        }
    }
}

extern "C" void kernel_launch(void* const* d_in, const int* in_sizes, int n_in,
                              void* d_out, int out_size) {
    const float* x    = (const float*)d_in[0];   // [8,2048,4096]
    const float* w    = (const float*)d_in[1];   // [512,512,8]
    const float* bias = (const float*)d_in[2];   // [4096]
    float* out = (float*)d_out;                  // [16384,4096] fp32

    cudaFuncSetAttribute(gemm_mma_kernel,
                         cudaFuncAttributeMaxDynamicSharedMemorySize, GEMM_SMEM);

    conv_x_kernel<<<(int)(((size_t)MDIM * KDIM / 8) / 256), 256>>>(x);
    build_weff_kernel<<<(512 * 512 + 255) / 256, 256>>>(w);

    dim3 grid(NDIM / 128, MDIM / 128);           // (32, 128)
    gemm_mma_kernel<<<grid, 256, GEMM_SMEM>>>(bias, out);
}

// round 11
// speedup vs baseline: 2.7086x; 1.0591x over previous
#include <cuda_runtime.h>
#include <cuda_fp16.h>
#include <cstdint>

#define MDIM 16384
#define NDIM 4096
#define KDIM 4096

// Module-load scratch (allowed): fp16 copies of x and expanded weight.
__device__ __half g_xh[(size_t)MDIM * KDIM];    // 128 MB, [M, K] row-major
__device__ __half g_wh[(size_t)NDIM * KDIM];    // 32 MB,  [N, K] row-major

// ---------------------------------------------------------------------------
// helpers
// ---------------------------------------------------------------------------
__device__ __forceinline__ uint32_t smem_u32(const void* p) {
    uint32_t a;
    asm("{ .reg .u64 t; cvta.to.shared.u64 t, %1; cvt.u32.u64 %0, t; }" : "=r"(a) : "l"(p));
    return a;
}
__device__ __forceinline__ void cp16(uint32_t s, const void* g) {
    asm volatile("cp.async.cg.shared.global [%0], [%1], 16;" :: "r"(s), "l"(g) : "memory");
}
#define CP_COMMIT() asm volatile("cp.async.commit_group;" ::: "memory")

__device__ __forceinline__ void ldsm4(uint32_t* r, uint32_t addr) {
    asm volatile("ldmatrix.sync.aligned.m8n8.x4.shared.b16 {%0,%1,%2,%3}, [%4];"
        : "=r"(r[0]), "=r"(r[1]), "=r"(r[2]), "=r"(r[3]) : "r"(addr));
}
__device__ __forceinline__ void mma_f16(float* d, const uint32_t* a, const uint32_t* b) {
    asm volatile(
        "mma.sync.aligned.m16n8k16.row.col.f32.f16.f16.f32 "
        "{%0,%1,%2,%3}, {%4,%5,%6,%7}, {%8,%9}, {%0,%1,%2,%3};"
        : "+f"(d[0]), "+f"(d[1]), "+f"(d[2]), "+f"(d[3])
        : "r"(a[0]), "r"(a[1]), "r"(a[2]), "r"(a[3]), "r"(b[0]), "r"(b[1]));
}

// ---------------------------------------------------------------------------
// Kernel 0: convert x fp32 -> fp16 (RN). 8 elements per thread.
// ---------------------------------------------------------------------------
__global__ void conv_x_kernel(const float* __restrict__ x) {
    size_t i = (size_t)blockIdx.x * blockDim.x + threadIdx.x;
    float4 a = reinterpret_cast<const float4*>(x)[2 * i];
    float4 b = reinterpret_cast<const float4*>(x)[2 * i + 1];
    __half2 h0 = __floats2half2_rn(a.x, a.y);
    __half2 h1 = __floats2half2_rn(a.z, a.w);
    __half2 h2 = __floats2half2_rn(b.x, b.y);
    __half2 h3 = __floats2half2_rn(b.z, b.w);
    uint4 o;
    o.x = *reinterpret_cast<uint32_t*>(&h0);
    o.y = *reinterpret_cast<uint32_t*>(&h1);
    o.z = *reinterpret_cast<uint32_t*>(&h2);
    o.w = *reinterpret_cast<uint32_t*>(&h3);
    reinterpret_cast<uint4*>(g_xh)[i] = o;
}

// ---------------------------------------------------------------------------
// Kernel 1: expand octonion weight [512,512,8] -> w_eff [4096,4096] in fp16.
// ---------------------------------------------------------------------------
__global__ void build_weff_kernel(const float* __restrict__ w) {
    const signed char KTAB[64] = {
        0,1,2,3,4,5,6,7, 1,0,3,2,5,4,7,6, 2,3,0,1,6,7,4,5, 3,2,1,0,7,6,5,4,
        4,5,6,7,0,1,2,3, 5,4,7,6,1,0,3,2, 6,7,4,5,2,3,0,1, 7,6,5,4,3,2,1,0 };
    const signed char STAB[64] = {
        +1,+1,+1,+1,+1,+1,+1,+1, +1,-1,+1,-1,+1,-1,-1,+1, +1,-1,-1,+1,+1,+1,-1,-1,
        +1,+1,-1,-1,+1,-1,+1,-1, +1,-1,-1,-1,-1,+1,+1,+1, +1,+1,-1,+1,-1,-1,-1,+1,
        +1,+1,+1,-1,-1,+1,-1,-1, +1,-1,+1,+1,-1,-1,+1,-1 };

    int t = blockIdx.x * blockDim.x + threadIdx.x;
    if (t >= 512 * 512) return;
    int o = t >> 9, i = t & 511;

    const float4* wp = reinterpret_cast<const float4*>(w + (size_t)t * 8);
    float4 wlo = wp[0], whi = wp[1];
    float wv[8] = {wlo.x, wlo.y, wlo.z, wlo.w, whi.x, whi.y, whi.z, whi.w};

    #pragma unroll
    for (int k = 0; k < 8; ++k) {
        __half2 h[4];
        #pragma unroll
        for (int bp = 0; bp < 4; ++bp) {
            int b0 = 2 * bp, b1 = 2 * bp + 1;
            int a0 = KTAB[k * 8 + b0], a1 = KTAB[k * 8 + b1];
            float v0 = (float)STAB[a0 * 8 + b0] * wv[a0];
            float v1 = (float)STAB[a1 * 8 + b1] * wv[a1];
            h[bp] = __floats2half2_rn(v0, v1);
        }
        uint4 pk;
        pk.x = *reinterpret_cast<uint32_t*>(&h[0]);
        pk.y = *reinterpret_cast<uint32_t*>(&h[1]);
        pk.z = *reinterpret_cast<uint32_t*>(&h[2]);
        pk.w = *reinterpret_cast<uint32_t*>(&h[3]);
        *reinterpret_cast<uint4*>(g_wh + (size_t)(o * 8 + k) * KDIM + i * 8) = pk;
    }
}

// ---------------------------------------------------------------------------
// Kernel 2: fp16 mma.sync GEMM. C[M,N] = g_xh[M,K] @ g_wh[N,K]^T + bias.
// CTA 128x128, BK=64 halves. 8 warps = 2(M) x 4(N); warp tile 64x32.
// 3-stage cp.async pipeline, 2 CTAs/SM. B fragments via paired ldsm.x4
// (R6-verified mapping: two n8 atoms per instruction).
// ---------------------------------------------------------------------------
#define BK 64
#define STAGES 3
#define A_BYTES (128 * 128)                 // 16384
#define STAGE_BYTES (2 * A_BYTES)           // 32768: [A | B]
#define GEMM_SMEM (STAGES * STAGE_BYTES)    // 98304
#define NTILES (KDIM / BK)                  // 64

__global__ __launch_bounds__(256, 2) void gemm_mma_kernel(
    const float* __restrict__ bias, float* __restrict__ C)
{
    extern __shared__ char smem[];
    const uint32_t sb = smem_u32(smem);
    const int tid  = threadIdx.x;
    const int lane = tid & 31;
    const int wid  = tid >> 5;
    const int rowBase = blockIdx.y * 128;    // M
    const int colBase = blockIdx.x * 128;    // N
    const int warpM = (wid >> 2) * 64;
    const int warpN = (wid & 3) * 32;

    // ---- global->shared load mapping: thread covers 4 A-chunks + 4 B-chunks ----
    const int lr  = tid >> 1;                // row 0..127
    const int lcp = (tid & 1) * 4;           // chunk base: 0 or 4 (chunk = 16 B)
    const __half* gA = g_xh + (size_t)(rowBase + lr) * KDIM + lcp * 8;
    const __half* gB = g_wh + (size_t)(colBase + lr) * KDIM + lcp * 8;
    uint32_t sAo[4], sBo[4];
    #pragma unroll
    for (int j = 0; j < 4; ++j) {
        uint32_t sw = (uint32_t)(((lcp + j) ^ (lr & 7)) << 4);
        sAo[j] = sb + lr * 128 + sw;
        sBo[j] = sb + A_BYTES + lr * 128 + sw;
    }

    // ---- ldmatrix address bases ----
    const int swz = lane & 7;
    uint32_t aBase[4], bBase[2];
    {
        int rA = warpM + (lane & 15);
        #pragma unroll
        for (int am = 0; am < 4; ++am) aBase[am] = sb + (uint32_t)((rA + am * 16) * 128);
        // B pair p covers n-atoms 2p,2p+1 (R6-verified):
        // rows warpN + p*16 + (lane&7) + ((lane>>4)&1)*8
        int rB = warpN + (lane & 7) + ((lane >> 4) & 1) * 8;
        #pragma unroll
        for (int p = 0; p < 2; ++p)
            bBase[p] = sb + A_BYTES + (uint32_t)((rB + p * 16) * 128);
    }
    const int laneAhi = lane >> 4;           // A: k-chunk +0/+1 select
    const int laneBhi = (lane >> 3) & 1;     // B: k-chunk +0/+1 select

    float acc[4][4][4];
    #pragma unroll
    for (int am = 0; am < 4; ++am)
        #pragma unroll
        for (int an = 0; an < 4; ++an)
            #pragma unroll
            for (int e = 0; e < 4; ++e) acc[am][an][e] = 0.0f;

    // ---- prologue: prefetch tiles 0,1 into stages 0,1 ----
    #pragma unroll
    for (int t = 0; t < STAGES - 1; ++t) {
        uint32_t so = (uint32_t)(t * STAGE_BYTES);
        const __half* a = gA + t * BK;
        const __half* b = gB + t * BK;
        #pragma unroll
        for (int j = 0; j < 4; ++j) cp16(sAo[j] + so, a + j * 8);
        #pragma unroll
        for (int j = 0; j < 4; ++j) cp16(sBo[j] + so, b + j * 8);
        CP_COMMIT();
    }

    // ---- mainloop (stage offsets cycle 0,S,2S without division) ----
    uint32_t soC = 0;                               // compute stage offset
    uint32_t soP = (STAGES - 1) * STAGE_BYTES;      // produce stage offset
    #pragma unroll 1
    for (int t = 0; t < NTILES; ++t) {
        asm volatile("cp.async.wait_group 1;" ::: "memory");
        __syncthreads();

        if (t + STAGES - 1 < NTILES) {
            int tn = t + STAGES - 1;
            const __half* a = gA + tn * BK;
            const __half* b = gB + tn * BK;
            #pragma unroll
            for (int j = 0; j < 4; ++j) cp16(sAo[j] + soP, a + j * 8);
            #pragma unroll
            for (int j = 0; j < 4; ++j) cp16(sBo[j] + soP, b + j * 8);
        }
        CP_COMMIT();

        // 4 k16 steps per tile; k16 = 32 B = 2 chunks
        #pragma unroll
        for (int ks = 0; ks < 4; ++ks) {
            uint32_t a_frag[4][4], b_frag[2][4];
            const uint32_t qa = (uint32_t)(((2 * ks + laneAhi) ^ swz) << 4);
            const uint32_t qb = (uint32_t)(((2 * ks + laneBhi) ^ swz) << 4);
            #pragma unroll
            for (int am = 0; am < 4; ++am) ldsm4(a_frag[am], aBase[am] + soC + qa);
            #pragma unroll
            for (int p = 0; p < 2; ++p)   ldsm4(b_frag[p],  bBase[p]  + soC + qb);
            #pragma unroll
            for (int am = 0; am < 4; ++am)
                #pragma unroll
                for (int an = 0; an < 4; ++an)
                    mma_f16(acc[am][an], a_frag[am], &b_frag[an >> 1][(an & 1) * 2]);
        }

        soC += STAGE_BYTES; if (soC == STAGES * STAGE_BYTES) soC = 0;
        soP += STAGE_BYTES; if (soP == STAGES * STAGE_BYTES) soP = 0;
    }

    // ---- epilogue: bias + store ----
    float2 bv[4];
    #pragma unroll
    for (int an = 0; an < 4; ++an)
        bv[an] = *reinterpret_cast<const float2*>(
            bias + colBase + warpN + an * 8 + (lane & 3) * 2);

    #pragma unroll
    for (int am = 0; am < 4; ++am) {
        const int r0 = rowBase + warpM + am * 16 + (lane >> 2);
        #pragma unroll
        for (int an = 0; an < 4; ++an) {
            const int col = colBase + warpN + an * 8 + (lane & 3) * 2;
            float2 lo = make_float2(acc[am][an][0] + bv[an].x, acc[am][an][1] + bv[an].y);
            float2 hi = make_float2(acc[am][an][2] + bv[an].x, acc[am][an][3] + bv[an].y);
            *reinterpret_cast<float2*>(C + (size_t)r0 * NDIM + col) = lo;
            *reinterpret_cast<float2*>(C + (size_t)(r0 + 8) * NDIM + col) = hi;
        }
    }
}

extern "C" void kernel_launch(void* const* d_in, const int* in_sizes, int n_in,
                              void* d_out, int out_size) {
    const float* x    = (const float*)d_in[0];   // [8,2048,4096]
    const float* w    = (const float*)d_in[1];   // [512,512,8]
    const float* bias = (const float*)d_in[2];   // [4096]
    float* out = (float*)d_out;                  // [16384,4096] fp32

    cudaFuncSetAttribute(gemm_mma_kernel,
                         cudaFuncAttributeMaxDynamicSharedMemorySize, GEMM_SMEM);

    conv_x_kernel<<<(int)(((size_t)MDIM * KDIM / 8) / 256), 256>>>(x);
    build_weff_kernel<<<(512 * 512 + 255) / 256, 256>>>(w);

    dim3 grid(NDIM / 128, MDIM / 128);           // (32, 128)
    gemm_mma_kernel<<<grid, 256, GEMM_SMEM>>>(bias, out);
}